// round 16
// baseline (speedup 1.0000x reference)
#include <cuda_runtime.h>
#include <cuda_fp16.h>
#include <math.h>

#define NL 3
#define D_MODEL 128
#define N_HEADS 4
#define DHEAD 32
#define DFF 512
#define DIN 64
#define BATCH 2
#define LSEQ 2048
#define S_LEN 2049
#define MROWS (BATCH * S_LEN)   // 4098
// QK scale with log2(e) folded in: scores arrive in base-2 domain
#define QK_SCALE_L2E 0.25500526764086547f

#define SPLITS 3
#define KCHUNK 704
#define VT_PITCH 2112
#define PSTRIDE ((size_t)BATCH * N_HEADS * S_LEN)

// ---------------- scratch (device globals; no allocation) ----------------
__device__ float  g_h[MROWS * D_MODEL];
__device__ __half g_hnh[MROWS * D_MODEL];
__device__ __half g_qkvh[MROWS * 3 * D_MODEL];
__device__ __half g_vt[BATCH * N_HEADS * DHEAD * VT_PITCH];
__device__ float  g_po[SPLITS * BATCH * N_HEADS * S_LEN * DHEAD];
__device__ float  g_pl[SPLITS * BATCH * N_HEADS * S_LEN];
#define WOFF_IN  0
#define WOFF_OUT (NL * 384 * 128)
#define WOFF_FF1 (WOFF_OUT + NL * 128 * 128)
#define WOFF_FF2 (WOFF_FF1 + NL * 512 * 128)
#define WTOTAL   (WOFF_FF2 + NL * 128 * 512)
__device__ __half g_wh[WTOTAL];

#define CW_N0 (NL * 384 * 128 / 4)
#define CW_N1 (NL * 128 * 128 / 4)
#define CW_N2 (NL * 512 * 128 / 4)
#define CW_N3 (NL * 128 * 512 / 4)
#define CW_TOTAL (CW_N0 + CW_N1 + CW_N2 + CW_N3)

// ---------------- mega kernel dynamic smem layout (16-row tile) ----------
#define OFF_ATTN 0                    // __half [16][136]  = 4352
#define OFF_HN2  4352                 // __half [16][136]  = 4352
#define OFF_HRES 8704                 // float  [16][128]  = 8192
#define OFF_F    16896                // __half [16][520]  = 16640
#define OFF_WS   33536                // __half staging    = 40960
#define OFF_PS   74496                // float  [16][8]    = 512
#define OFF_PQ   75008                // float  [16][8]    = 512
#define SMEM_MEGA 75520

// ---------------- mma helper ----------------
__device__ __forceinline__ void mma16816(
    float c[4], const unsigned a[4], const unsigned b[2])
{
    asm volatile(
        "mma.sync.aligned.m16n8k16.row.col.f32.f16.f16.f32 "
        "{%0,%1,%2,%3}, {%4,%5,%6,%7}, {%8,%9}, {%0,%1,%2,%3};\n"
        : "+f"(c[0]), "+f"(c[1]), "+f"(c[2]), "+f"(c[3])
        : "r"(a[0]), "r"(a[1]), "r"(a[2]), "r"(a[3]),
          "r"(b[0]), "r"(b[1]));
}

// ---------------- fused weight fp32 -> fp16 conversion ----------------
__global__ __launch_bounds__(256) void convw_all_kernel(
    const float* __restrict__ s0, const float* __restrict__ s1,
    const float* __restrict__ s2, const float* __restrict__ s3,
    __half* __restrict__ dst)
{
    int i = blockIdx.x * 256 + threadIdx.x;
    if (i >= CW_TOTAL) return;
    const float* src;
    int off, local = i;
    if (local < CW_N0)                { src = s0; off = WOFF_IN; }
    else if ((local -= CW_N0) < CW_N1){ src = s1; off = WOFF_OUT; }
    else if ((local -= CW_N1) < CW_N2){ src = s2; off = WOFF_FF1; }
    else { local -= CW_N2;              src = s3; off = WOFF_FF2; }
    float4 v = *reinterpret_cast<const float4*>(src + (size_t)local * 4);
    __half2 a = __floats2half2_rn(v.x, v.y);
    __half2 b = __floats2half2_rn(v.z, v.w);
    uint2 pk;
    pk.x = *reinterpret_cast<unsigned*>(&a);
    pk.y = *reinterpret_cast<unsigned*>(&b);
    *reinterpret_cast<uint2*>(dst + (size_t)off + (size_t)local * 4) = pk;
}

// ---------------- embedding + fused LN1(layer0) ----------------
__global__ __launch_bounds__(128) void embed_ln_kernel(
    const float* __restrict__ x, const float* __restrict__ ew,
    const float* __restrict__ eb, const float* __restrict__ pos,
    const float* __restrict__ cls, const float* __restrict__ lns,
    const float* __restrict__ lnb, float* __restrict__ h,
    __half* __restrict__ hn)
{
    __shared__ float xs[DIN];
    __shared__ float red[8];
    int s = blockIdx.x, b = blockIdx.y;
    int d = threadIdx.x;
    if (s > 0 && d < DIN) xs[d] = x[((size_t)b * LSEQ + (s - 1)) * DIN + d];
    __syncthreads();
    float val;
    if (s == 0) {
        val = cls[d] + pos[d];
    } else {
        float acc = 0.f;
        const float* wr = ew + (size_t)d * DIN;
        #pragma unroll
        for (int j = 0; j < DIN; j++) acc = fmaf(xs[j], wr[j], acc);
        val = acc + eb[d] + pos[(size_t)s * D_MODEL + d];
    }
    size_t row = (size_t)b * S_LEN + s;
    h[row * D_MODEL + d] = val;
    int w = d >> 5, lane = d & 31;
    float sv = val, qv = val * val;
    #pragma unroll
    for (int o = 16; o; o >>= 1) {
        sv += __shfl_xor_sync(0xffffffffu, sv, o);
        qv += __shfl_xor_sync(0xffffffffu, qv, o);
    }
    if (lane == 0) { red[w] = sv; red[4 + w] = qv; }
    __syncthreads();
    float sum = red[0] + red[1] + red[2] + red[3];
    float sq  = red[4] + red[5] + red[6] + red[7];
    float mean = sum * (1.f / 128.f);
    float rstd = rsqrtf(sq * (1.f / 128.f) - mean * mean + 1e-5f);
    hn[row * D_MODEL + d] = __float2half_rn((val - mean) * rstd * lns[d] + lnb[d]);
}

// ---------------- QKV tensor-core GEMM (layer 0 only) ----------------
#define GPITCH 40
__global__ __launch_bounds__(256) void qkv_gemm_kernel(
    const __half* __restrict__ A, const __half* __restrict__ W,
    const float* __restrict__ bias, __half* __restrict__ C,
    __half* __restrict__ vT, int M)
{
    const int N = 384, K = 128;
    __shared__ __half As[128][GPITCH];
    __shared__ __half Ws[64][GPITCH];
    const int tid = threadIdx.x;
    const int warp = tid >> 5;
    const int lane = tid & 31;
    const int g = lane >> 2;
    const int tig = lane & 3;
    const int warp_m = warp >> 1;
    const int warp_n = warp & 1;
    const int m0 = blockIdx.y * 128;
    const int n0 = blockIdx.x * 64;
    const int NK = K / 32;
    const int wr = tid >> 2, wq = tid & 3;

    float c[2][4][4] = {};

    uint4 aReg[2], wReg;
    #pragma unroll
    for (int it = 0; it < 2; it++) {
        int idx = tid + it * 256;
        int r = idx >> 2, quad = idx & 3;
        int m = m0 + r;
        aReg[it] = (m < M)
            ? *reinterpret_cast<const uint4*>(A + (size_t)m * K + quad * 8)
            : make_uint4(0u, 0u, 0u, 0u);
    }
    wReg = *reinterpret_cast<const uint4*>(W + (size_t)(n0 + wr) * K + wq * 8);

    for (int kt = 0; kt < NK; kt++) {
        #pragma unroll
        for (int it = 0; it < 2; it++) {
            int idx = tid + it * 256;
            int r = idx >> 2, quad = idx & 3;
            *reinterpret_cast<uint4*>(&As[r][quad * 8]) = aReg[it];
        }
        *reinterpret_cast<uint4*>(&Ws[wr][wq * 8]) = wReg;
        __syncthreads();
        if (kt + 1 < NK) {
            int k0 = (kt + 1) * 32;
            #pragma unroll
            for (int it = 0; it < 2; it++) {
                int idx = tid + it * 256;
                int r = idx >> 2, quad = idx & 3;
                int m = m0 + r;
                aReg[it] = (m < M)
                    ? *reinterpret_cast<const uint4*>(A + (size_t)m * K + k0 + quad * 8)
                    : make_uint4(0u, 0u, 0u, 0u);
            }
            wReg = *reinterpret_cast<const uint4*>(W + (size_t)(n0 + wr) * K + k0 + wq * 8);
        }
        #pragma unroll
        for (int ks = 0; ks < 2; ks++) {
            unsigned a[2][4];
            #pragma unroll
            for (int mt = 0; mt < 2; mt++) {
                int rbase = warp_m * 32 + mt * 16;
                a[mt][0] = *reinterpret_cast<const unsigned*>(&As[rbase + g    ][ks * 16 + tig * 2]);
                a[mt][1] = *reinterpret_cast<const unsigned*>(&As[rbase + g + 8][ks * 16 + tig * 2]);
                a[mt][2] = *reinterpret_cast<const unsigned*>(&As[rbase + g    ][ks * 16 + tig * 2 + 8]);
                a[mt][3] = *reinterpret_cast<const unsigned*>(&As[rbase + g + 8][ks * 16 + tig * 2 + 8]);
            }
            #pragma unroll
            for (int nt = 0; nt < 4; nt++) {
                unsigned bfr[2];
                int nrow = warp_n * 32 + nt * 8 + g;
                bfr[0] = *reinterpret_cast<const unsigned*>(&Ws[nrow][ks * 16 + tig * 2]);
                bfr[1] = *reinterpret_cast<const unsigned*>(&Ws[nrow][ks * 16 + tig * 2 + 8]);
                mma16816(c[0][nt], a[0], bfr);
                mma16816(c[1][nt], a[1], bfr);
            }
        }
        __syncthreads();
    }

    #pragma unroll
    for (int mt = 0; mt < 2; mt++) {
        #pragma unroll
        for (int half_row = 0; half_row < 2; half_row++) {
            int m = m0 + warp_m * 32 + mt * 16 + g + half_row * 8;
            if (m >= M) continue;
            int bb = m / S_LEN, ss = m % S_LEN;
            #pragma unroll
            for (int nt = 0; nt < 4; nt++) {
                int n = n0 + warp_n * 32 + nt * 8 + tig * 2;
                float v0 = c[mt][nt][half_row * 2 + 0] + bias[n];
                float v1 = c[mt][nt][half_row * 2 + 1] + bias[n + 1];
                if (n >= 256) {
                    int hh = (n - 256) >> 5, dd = (n - 256) & 31;
                    __half* vbase = vT + ((size_t)(bb * N_HEADS + hh) * DHEAD + dd) * VT_PITCH + ss;
                    vbase[0] = __float2half_rn(v0);
                    vbase[VT_PITCH] = __float2half_rn(v1);
                } else {
                    if (n < 128) { v0 *= QK_SCALE_L2E; v1 *= QK_SCALE_L2E; }
                    __half2 hv = __floats2half2_rn(v0, v1);
                    *reinterpret_cast<unsigned*>(
                        C + (size_t)m * N + n) = *reinterpret_cast<unsigned*>(&hv);
                }
            }
        }
    }
}

// ---------------- split-S flash attention (fixed max; base-2 exp) --------
#define BQ 128
#define BK 64
#define QPITCH 40
#define VPITCH 72

__global__ __launch_bounds__(256, 3) void attn_kernel(
    const __half* __restrict__ qkv, const __half* __restrict__ vT,
    float* __restrict__ po, float* __restrict__ pl)
{
    __shared__ __half Qs[BQ][QPITCH];
    __shared__ __half Kt[2][BK][QPITCH];
    __shared__ __half Vt[2][DHEAD][VPITCH];
    const int tid = threadIdx.x;
    const int warp = tid >> 5;
    const int lane = tid & 31;
    const int g = lane >> 2;
    const int tig = lane & 3;
    const int b = blockIdx.z, h = blockIdx.y;
    const int tile = blockIdx.x / SPLITS;
    const int split = blockIdx.x % SPLITS;
    const int q0 = tile * BQ;
    const int qbase = warp * 16;
    const int kstart = split * KCHUNK;
    const int kend = min(kstart + KCHUNK, S_LEN);
    const int ntile = (kend - kstart + BK - 1) / BK;

    #pragma unroll
    for (int idx = tid; idx < BQ * 4; idx += 256) {
        int r = idx >> 2, quad = idx & 3;
        int q = q0 + r;
        uint4 v = make_uint4(0u, 0u, 0u, 0u);
        if (q < S_LEN)
            v = *reinterpret_cast<const uint4*>(
                qkv + ((size_t)(b * S_LEN + q)) * 384 + h * 32 + quad * 8);
        *reinterpret_cast<uint4*>(&Qs[r][quad * 8]) = v;
    }

    const __half* Kbase = qkv + (size_t)b * S_LEN * 384 + 128 + h * 32;
    const __half* Vbase = vT + (size_t)(b * N_HEADS + h) * DHEAD * VT_PITCH;
    const int kr = tid >> 2, kq = tid & 3;
    const int vr = tid >> 3, vq = tid & 7;

    uint4 kreg, vreg;
    {
        int kg = kstart + kr;
        kreg = (kg < S_LEN)
            ? *reinterpret_cast<const uint4*>(Kbase + (size_t)kg * 384 + kq * 8)
            : make_uint4(0u, 0u, 0u, 0u);
        vreg = *reinterpret_cast<const uint4*>(Vbase + (size_t)vr * VT_PITCH + kstart + vq * 8);
    }
    *reinterpret_cast<uint4*>(&Kt[0][kr][kq * 8]) = kreg;
    *reinterpret_cast<uint4*>(&Vt[0][vr][vq * 8]) = vreg;
    __syncthreads();

    unsigned A[2][4];
    #pragma unroll
    for (int ks = 0; ks < 2; ks++) {
        A[ks][0] = *reinterpret_cast<const unsigned*>(&Qs[qbase + g    ][ks * 16 + tig * 2]);
        A[ks][1] = *reinterpret_cast<const unsigned*>(&Qs[qbase + g + 8][ks * 16 + tig * 2]);
        A[ks][2] = *reinterpret_cast<const unsigned*>(&Qs[qbase + g    ][ks * 16 + tig * 2 + 8]);
        A[ks][3] = *reinterpret_cast<const unsigned*>(&Qs[qbase + g + 8][ks * 16 + tig * 2 + 8]);
    }

    float l0 = 0.f, l1 = 0.f;
    float o[4][4] = {};

    for (int t = 0; t < ntile; t++) {
        const int kb = kstart + t * BK;
        const int buf = t & 1;
        if (t + 1 < ntile) {
            int kb2 = kb + BK;
            int kg = kb2 + kr;
            kreg = (kg < S_LEN)
                ? *reinterpret_cast<const uint4*>(Kbase + (size_t)kg * 384 + kq * 8)
                : make_uint4(0u, 0u, 0u, 0u);
            vreg = *reinterpret_cast<const uint4*>(Vbase + (size_t)vr * VT_PITCH + kb2 + vq * 8);
        }

        float s[8][4];
        #pragma unroll
        for (int j = 0; j < 8; j++) {
            s[j][0] = s[j][1] = s[j][2] = s[j][3] = 0.f;
            #pragma unroll
            for (int ks = 0; ks < 2; ks++) {
                unsigned bfr[2];
                bfr[0] = *reinterpret_cast<const unsigned*>(&Kt[buf][j * 8 + g][ks * 16 + tig * 2]);
                bfr[1] = *reinterpret_cast<const unsigned*>(&Kt[buf][j * 8 + g][ks * 16 + tig * 2 + 8]);
                mma16816(s[j], A[ks], bfr);
            }
        }
        if (kb + BK > S_LEN) {
            #pragma unroll
            for (int j = 0; j < 8; j++) {
                int key = kb + j * 8 + tig * 2;
                if (key >= S_LEN)     { s[j][0] = -1e30f; s[j][2] = -1e30f; }
                if (key + 1 >= S_LEN) { s[j][1] = -1e30f; s[j][3] = -1e30f; }
            }
        }

        unsigned ph[8][2];
        #pragma unroll
        for (int j = 0; j < 8; j++) {
            __half2 h2a = __floats2half2_rn(exp2f(s[j][0]), exp2f(s[j][1]));
            __half2 h2b = __floats2half2_rn(exp2f(s[j][2]), exp2f(s[j][3]));
            ph[j][0] = *reinterpret_cast<unsigned*>(&h2a);
            ph[j][1] = *reinterpret_cast<unsigned*>(&h2b);
            float2 fa = __half22float2(h2a);
            float2 fb = __half22float2(h2b);
            l0 += fa.x + fa.y;
            l1 += fb.x + fb.y;
        }

        #pragma unroll
        for (int kt = 0; kt < 4; kt++) {
            unsigned pa[4] = { ph[2 * kt][0], ph[2 * kt][1],
                               ph[2 * kt + 1][0], ph[2 * kt + 1][1] };
            #pragma unroll
            for (int nt = 0; nt < 4; nt++) {
                unsigned bfr[2];
                bfr[0] = *reinterpret_cast<const unsigned*>(&Vt[buf][nt * 8 + g][kt * 16 + tig * 2]);
                bfr[1] = *reinterpret_cast<const unsigned*>(&Vt[buf][nt * 8 + g][kt * 16 + tig * 2 + 8]);
                mma16816(o[nt], pa, bfr);
            }
        }
        if (t + 1 < ntile) {
            *reinterpret_cast<uint4*>(&Kt[buf ^ 1][kr][kq * 8]) = kreg;
            *reinterpret_cast<uint4*>(&Vt[buf ^ 1][vr][vq * 8]) = vreg;
        }
        __syncthreads();
    }

    l0 += __shfl_xor_sync(0xffffffffu, l0, 1);
    l0 += __shfl_xor_sync(0xffffffffu, l0, 2);
    l1 += __shfl_xor_sync(0xffffffffu, l1, 1);
    l1 += __shfl_xor_sync(0xffffffffu, l1, 2);

    const size_t pbase = (((size_t)split * BATCH + b) * N_HEADS + h) * S_LEN;
    int qa = q0 + qbase + g;
    int qb2 = qa + 8;
    if (qa < S_LEN) {
        #pragma unroll
        for (int nt = 0; nt < 4; nt++) {
            float2 v = make_float2(o[nt][0], o[nt][1]);
            *reinterpret_cast<float2*>(po + (pbase + qa) * DHEAD + nt * 8 + tig * 2) = v;
        }
        if (tig == 0) pl[pbase + qa] = l0;
    }
    if (qb2 < S_LEN) {
        #pragma unroll
        for (int nt = 0; nt < 4; nt++) {
            float2 v = make_float2(o[nt][2], o[nt][3]);
            *reinterpret_cast<float2*>(po + (pbase + qb2) * DHEAD + nt * 8 + tig * 2) = v;
        }
        if (tig == 0) pl[pbase + qb2] = l1;
    }
}

// ---------------- MEGA layer-tail kernel: 16-row tile, 2 CTAs/SM ---------
// merge(po,pl) -> out-proj + resid -> LN2 -> FF1+ReLU -> FF2 + resid -> h
// QKV_NEXT: additionally LN1next (smem) -> QKV GEMM of next layer.
template <bool QKV_NEXT>
__global__ __launch_bounds__(256, 2) void mega_tail_kernel(
    const float* __restrict__ po, const float* __restrict__ pl,
    const __half* __restrict__ Wout, const float* __restrict__ bout,
    const float* __restrict__ ln2s, const float* __restrict__ ln2b,
    const __half* __restrict__ W1, const float* __restrict__ b1,
    const __half* __restrict__ W2, const float* __restrict__ b2,
    const float* __restrict__ ln1s, const float* __restrict__ ln1b,
    const __half* __restrict__ Win, const float* __restrict__ bin,
    float* __restrict__ h, __half* __restrict__ qkvh,
    __half* __restrict__ vT, int M)
{
    extern __shared__ char smem[];
    __half (*Attn)[136] = reinterpret_cast<__half(*)[136]>(smem + OFF_ATTN);
    __half (*HN2)[136]  = reinterpret_cast<__half(*)[136]>(smem + OFF_HN2);
    float (*Hres)[128]  = reinterpret_cast<float(*)[128]>(smem + OFF_HRES);
    __half (*F)[520]    = reinterpret_cast<__half(*)[520]>(smem + OFF_F);
    __half* Wsraw       = reinterpret_cast<__half*>(smem + OFF_WS);
    float (*psum)[8]    = reinterpret_cast<float(*)[8]>(smem + OFF_PS);
    float (*psq)[8]     = reinterpret_cast<float(*)[8]>(smem + OFF_PQ);

    const int tid = threadIdx.x;
    const int warp = tid >> 5;       // 0..7 = warp_n
    const int lane = tid & 31;
    const int g = lane >> 2;
    const int tig = lane & 3;
    const int m0 = blockIdx.x * 16;

    // ---- stage Wout fully (overlaps merge loads) ----
    {
        __half (*WsA)[136] = reinterpret_cast<__half(*)[136]>(Wsraw);
        #pragma unroll
        for (int it = 0; it < 8; it++) {
            int idx = tid + it * 256;
            int r = idx >> 4, q = idx & 15;
            *reinterpret_cast<uint4*>(&WsA[r][q * 8]) =
                *reinterpret_cast<const uint4*>(Wout + (size_t)r * 128 + q * 8);
        }
    }

    // ---- stage 0: merge attention partials; load residual ----
    {
        int row = tid >> 4;               // 0..15
        int dseg = (tid & 15) * 8;        // 0..120 (8 dims per thread)
        int mrow = m0 + row;
        if (mrow < M) {
            int bb = mrow / S_LEN, qq = mrow % S_LEN;
            int hh = dseg >> 5, dd = dseg & 31;
            size_t prow = ((size_t)bb * N_HEADS + hh) * S_LEN + qq;
            float linv = 1.f / (pl[prow] + pl[prow + PSTRIDE] + pl[prow + 2 * PSTRIDE]);
            float acc[8];
            #pragma unroll
            for (int t = 0; t < 2; t++) {
                float4 p0 = *reinterpret_cast<const float4*>(po + prow * DHEAD + dd + t * 4);
                float4 p1 = *reinterpret_cast<const float4*>(po + (prow + PSTRIDE) * DHEAD + dd + t * 4);
                float4 p2 = *reinterpret_cast<const float4*>(po + (prow + 2 * PSTRIDE) * DHEAD + dd + t * 4);
                acc[t * 4 + 0] = (p0.x + p1.x + p2.x) * linv;
                acc[t * 4 + 1] = (p0.y + p1.y + p2.y) * linv;
                acc[t * 4 + 2] = (p0.z + p1.z + p2.z) * linv;
                acc[t * 4 + 3] = (p0.w + p1.w + p2.w) * linv;
            }
            unsigned pk[4];
            #pragma unroll
            for (int t = 0; t < 4; t++) {
                __half2 hv = __floats2half2_rn(acc[t * 2], acc[t * 2 + 1]);
                pk[t] = *reinterpret_cast<unsigned*>(&hv);
            }
            *reinterpret_cast<uint4*>(&Attn[row][dseg]) = make_uint4(pk[0], pk[1], pk[2], pk[3]);
            #pragma unroll
            for (int t = 0; t < 2; t++)
                *reinterpret_cast<float4*>(&Hres[row][dseg + t * 4]) =
                    *reinterpret_cast<const float4*>(h + (size_t)mrow * 128 + dseg + t * 4);
        } else {
            *reinterpret_cast<uint4*>(&Attn[row][dseg]) = make_uint4(0u, 0u, 0u, 0u);
            float4 fz = make_float4(0.f, 0.f, 0.f, 0.f);
            #pragma unroll
            for (int t = 0; t < 2; t++)
                *reinterpret_cast<float4*>(&Hres[row][dseg + t * 4]) = fz;
        }
    }
    __syncthreads();

    // ---- stage 1: out-proj GEMM (warp tile 16x16, nt=2) ----
    float c1[2][4] = {};
    {
        __half (*WsA)[136] = reinterpret_cast<__half(*)[136]>(Wsraw);
        #pragma unroll
        for (int ks8 = 0; ks8 < 8; ks8++) {
            int kc = ks8 * 16;
            unsigned a[4];
            a[0] = *reinterpret_cast<const unsigned*>(&Attn[g    ][kc + tig * 2]);
            a[1] = *reinterpret_cast<const unsigned*>(&Attn[g + 8][kc + tig * 2]);
            a[2] = *reinterpret_cast<const unsigned*>(&Attn[g    ][kc + tig * 2 + 8]);
            a[3] = *reinterpret_cast<const unsigned*>(&Attn[g + 8][kc + tig * 2 + 8]);
            #pragma unroll
            for (int nt = 0; nt < 2; nt++) {
                unsigned bfr[2];
                int nrow = warp * 16 + nt * 8 + g;
                bfr[0] = *reinterpret_cast<const unsigned*>(&WsA[nrow][kc + tig * 2]);
                bfr[1] = *reinterpret_cast<const unsigned*>(&WsA[nrow][kc + tig * 2 + 8]);
                mma16816(c1[nt], a, bfr);
            }
        }
    }

    // prefetch FF1 chunk 0 (overlaps LN2)
    uint4 w1Reg[8];
    #pragma unroll
    for (int it = 0; it < 8; it++) {
        int idx = tid + it * 256;
        int r = idx >> 2, q = idx & 3;
        w1Reg[it] = *reinterpret_cast<const uint4*>(W1 + (size_t)r * 128 + q * 8);
    }

    const int lr0 = g, lr1 = g + 8;
    #pragma unroll
    for (int nt = 0; nt < 2; nt++) {
        int n = warp * 16 + nt * 8 + tig * 2;
        float b0 = bout[n], b1v = bout[n + 1];
        c1[nt][0] += b0 + Hres[lr0][n];
        c1[nt][1] += b1v + Hres[lr0][n + 1];
        c1[nt][2] += b0 + Hres[lr1][n];
        c1[nt][3] += b1v + Hres[lr1][n + 1];
    }
    // LN2 -> HN2
    {
        float s0 = 0.f, q0 = 0.f, s1 = 0.f, q1 = 0.f;
        #pragma unroll
        for (int nt = 0; nt < 2; nt++) {
            s0 += c1[nt][0] + c1[nt][1];
            q0 += c1[nt][0] * c1[nt][0] + c1[nt][1] * c1[nt][1];
            s1 += c1[nt][2] + c1[nt][3];
            q1 += c1[nt][2] * c1[nt][2] + c1[nt][3] * c1[nt][3];
        }
        #pragma unroll
        for (int o = 1; o < 4; o <<= 1) {
            s0 += __shfl_xor_sync(0xffffffffu, s0, o);
            q0 += __shfl_xor_sync(0xffffffffu, q0, o);
            s1 += __shfl_xor_sync(0xffffffffu, s1, o);
            q1 += __shfl_xor_sync(0xffffffffu, q1, o);
        }
        if (tig == 0) {
            psum[lr0][warp] = s0; psq[lr0][warp] = q0;
            psum[lr1][warp] = s1; psq[lr1][warp] = q1;
        }
        __syncthreads();
        float sum0 = 0.f, sq0 = 0.f, sum1 = 0.f, sq1 = 0.f;
        #pragma unroll
        for (int wv = 0; wv < 8; wv++) {
            sum0 += psum[lr0][wv]; sq0 += psq[lr0][wv];
            sum1 += psum[lr1][wv]; sq1 += psq[lr1][wv];
        }
        float mean0 = sum0 * (1.f / 128.f);
        float rstd0 = rsqrtf(sq0 * (1.f / 128.f) - mean0 * mean0 + 1e-5f);
        float mean1 = sum1 * (1.f / 128.f);
        float rstd1 = rsqrtf(sq1 * (1.f / 128.f) - mean1 * mean1 + 1e-5f);
        #pragma unroll
        for (int nt = 0; nt < 2; nt++) {
            int n = warp * 16 + nt * 8 + tig * 2;
            float g0 = ln2s[n], g1 = ln2s[n + 1];
            float bb0 = ln2b[n], bb1 = ln2b[n + 1];
            __half2 hv0 = __floats2half2_rn(
                (c1[nt][0] - mean0) * rstd0 * g0 + bb0,
                (c1[nt][1] - mean0) * rstd0 * g1 + bb1);
            __half2 hv1 = __floats2half2_rn(
                (c1[nt][2] - mean1) * rstd1 * g0 + bb0,
                (c1[nt][3] - mean1) * rstd1 * g1 + bb1);
            *reinterpret_cast<unsigned*>(&HN2[lr0][n]) = *reinterpret_cast<unsigned*>(&hv0);
            *reinterpret_cast<unsigned*>(&HN2[lr1][n]) = *reinterpret_cast<unsigned*>(&hv1);
            Hres[lr0][n] = c1[nt][0]; Hres[lr0][n + 1] = c1[nt][1];
            Hres[lr1][n] = c1[nt][2]; Hres[lr1][n + 1] = c1[nt][3];
        }
    }

    // ---- stage 2: FF1 (M=16, N=512, K=128): warp tile 16x64, nt=8 ----
    float c2[8][4] = {};
    {
        __half (*WsB)[40] = reinterpret_cast<__half(*)[40]>(Wsraw);
        #pragma unroll
        for (int kt = 0; kt < 4; kt++) {
            __syncthreads();
            #pragma unroll
            for (int it = 0; it < 8; it++) {
                int idx = tid + it * 256;
                int r = idx >> 2, q = idx & 3;
                *reinterpret_cast<uint4*>(&WsB[r][q * 8]) = w1Reg[it];
            }
            __syncthreads();
            if (kt + 1 < 4) {
                int k0 = (kt + 1) * 32;
                #pragma unroll
                for (int it = 0; it < 8; it++) {
                    int idx = tid + it * 256;
                    int r = idx >> 2, q = idx & 3;
                    w1Reg[it] = *reinterpret_cast<const uint4*>(
                        W1 + (size_t)r * 128 + k0 + q * 8);
                }
            }
            #pragma unroll
            for (int ks = 0; ks < 2; ks++) {
                int kc = kt * 32 + ks * 16;
                unsigned a[4];
                a[0] = *reinterpret_cast<const unsigned*>(&HN2[g    ][kc + tig * 2]);
                a[1] = *reinterpret_cast<const unsigned*>(&HN2[g + 8][kc + tig * 2]);
                a[2] = *reinterpret_cast<const unsigned*>(&HN2[g    ][kc + tig * 2 + 8]);
                a[3] = *reinterpret_cast<const unsigned*>(&HN2[g + 8][kc + tig * 2 + 8]);
                #pragma unroll
                for (int nt = 0; nt < 8; nt++) {
                    unsigned bfr[2];
                    int nrow = warp * 64 + nt * 8 + g;
                    bfr[0] = *reinterpret_cast<const unsigned*>(&WsB[nrow][ks * 16 + tig * 2]);
                    bfr[1] = *reinterpret_cast<const unsigned*>(&WsB[nrow][ks * 16 + tig * 2 + 8]);
                    mma16816(c2[nt], a, bfr);
                }
            }
        }
    }

    // prefetch FF2 chunk 0 (overlaps ReLU epilogue)
    uint4 w2Reg[4];
    #pragma unroll
    for (int it = 0; it < 4; it++) {
        int idx = tid + it * 256;
        int r = idx >> 3, q = idx & 7;
        w2Reg[it] = *reinterpret_cast<const uint4*>(W2 + (size_t)r * 512 + q * 8);
    }

    // bias + ReLU -> F (fp16)
    #pragma unroll
    for (int hr = 0; hr < 2; hr++) {
        int lr = hr * 8 + g;
        #pragma unroll
        for (int nt = 0; nt < 8; nt++) {
            int n = warp * 64 + nt * 8 + tig * 2;
            float v0 = fmaxf(c2[nt][hr * 2 + 0] + b1[n], 0.f);
            float v1 = fmaxf(c2[nt][hr * 2 + 1] + b1[n + 1], 0.f);
            __half2 hv = __floats2half2_rn(v0, v1);
            *reinterpret_cast<unsigned*>(&F[lr][n]) = *reinterpret_cast<unsigned*>(&hv);
        }
    }

    // ---- stage 3: FF2 (M=16, N=128, K=512), DOUBLE-BUFFERED, nt=2 ----
    float c3[2][4] = {};
    {
        __half (*WsC)[128][72] = reinterpret_cast<__half(*)[128][72]>(Wsraw);
        __syncthreads();
        #pragma unroll
        for (int it = 0; it < 4; it++) {
            int idx = tid + it * 256;
            int r = idx >> 3, q = idx & 7;
            *reinterpret_cast<uint4*>(&WsC[0][r][q * 8]) = w2Reg[it];
        }
        __syncthreads();
        #pragma unroll
        for (int kt = 0; kt < 8; kt++) {
            const int buf = kt & 1;
            if (kt + 1 < 8) {
                int k0 = (kt + 1) * 64;
                #pragma unroll
                for (int it = 0; it < 4; it++) {
                    int idx = tid + it * 256;
                    int r = idx >> 3, q = idx & 7;
                    uint4 wv = *reinterpret_cast<const uint4*>(
                        W2 + (size_t)r * 512 + k0 + q * 8);
                    *reinterpret_cast<uint4*>(&WsC[buf ^ 1][r][q * 8]) = wv;
                }
            }
            #pragma unroll
            for (int ks = 0; ks < 4; ks++) {
                int kc = kt * 64 + ks * 16;
                unsigned a[4];
                a[0] = *reinterpret_cast<const unsigned*>(&F[g    ][kc + tig * 2]);
                a[1] = *reinterpret_cast<const unsigned*>(&F[g + 8][kc + tig * 2]);
                a[2] = *reinterpret_cast<const unsigned*>(&F[g    ][kc + tig * 2 + 8]);
                a[3] = *reinterpret_cast<const unsigned*>(&F[g + 8][kc + tig * 2 + 8]);
                #pragma unroll
                for (int nt = 0; nt < 2; nt++) {
                    unsigned bfr[2];
                    int nrow = warp * 16 + nt * 8 + g;
                    bfr[0] = *reinterpret_cast<const unsigned*>(&WsC[buf][nrow][ks * 16 + tig * 2]);
                    bfr[1] = *reinterpret_cast<const unsigned*>(&WsC[buf][nrow][ks * 16 + tig * 2 + 8]);
                    mma16816(c3[nt], a, bfr);
                }
            }
            __syncthreads();
        }
    }

    // prefetch QKV chunk 0 (overlaps FF2 epilogue + LN1next)
    uint4 w4Reg[8];
    if (QKV_NEXT) {
        #pragma unroll
        for (int it = 0; it < 8; it++) {
            int idx = tid + it * 256;
            int r = idx >> 4, q = idx & 15;
            w4Reg[it] = *reinterpret_cast<const uint4*>(Win + (size_t)r * 128 + q * 8);
        }
    }

    // epilogue: bias + residual -> h global
    const int mrow0 = m0 + lr0, mrow1 = m0 + lr1;
    #pragma unroll
    for (int nt = 0; nt < 2; nt++) {
        int n = warp * 16 + nt * 8 + tig * 2;
        float b0 = b2[n], b1v = b2[n + 1];
        c3[nt][0] += b0 + Hres[lr0][n];
        c3[nt][1] += b1v + Hres[lr0][n + 1];
        c3[nt][2] += b0 + Hres[lr1][n];
        c3[nt][3] += b1v + Hres[lr1][n + 1];
        if (mrow0 < M)
            *reinterpret_cast<float2*>(h + (size_t)mrow0 * 128 + n) =
                make_float2(c3[nt][0], c3[nt][1]);
        if (mrow1 < M)
            *reinterpret_cast<float2*>(h + (size_t)mrow1 * 128 + n) =
                make_float2(c3[nt][2], c3[nt][3]);
    }

    if (QKV_NEXT) {
        // ---- LN1next -> HN2 ----
        float s0 = 0.f, q0 = 0.f, s1 = 0.f, q1 = 0.f;
        #pragma unroll
        for (int nt = 0; nt < 2; nt++) {
            s0 += c3[nt][0] + c3[nt][1];
            q0 += c3[nt][0] * c3[nt][0] + c3[nt][1] * c3[nt][1];
            s1 += c3[nt][2] + c3[nt][3];
            q1 += c3[nt][2] * c3[nt][2] + c3[nt][3] * c3[nt][3];
        }
        #pragma unroll
        for (int o = 1; o < 4; o <<= 1) {
            s0 += __shfl_xor_sync(0xffffffffu, s0, o);
            q0 += __shfl_xor_sync(0xffffffffu, q0, o);
            s1 += __shfl_xor_sync(0xffffffffu, s1, o);
            q1 += __shfl_xor_sync(0xffffffffu, q1, o);
        }
        __syncthreads();
        if (tig == 0) {
            psum[lr0][warp] = s0; psq[lr0][warp] = q0;
            psum[lr1][warp] = s1; psq[lr1][warp] = q1;
        }
        __syncthreads();
        float sum0 = 0.f, sq0 = 0.f, sum1 = 0.f, sq1 = 0.f;
        #pragma unroll
        for (int wv = 0; wv < 8; wv++) {
            sum0 += psum[lr0][wv]; sq0 += psq[lr0][wv];
            sum1 += psum[lr1][wv]; sq1 += psq[lr1][wv];
        }
        float mean0 = sum0 * (1.f / 128.f);
        float rstd0 = rsqrtf(sq0 * (1.f / 128.f) - mean0 * mean0 + 1e-5f);
        float mean1 = sum1 * (1.f / 128.f);
        float rstd1 = rsqrtf(sq1 * (1.f / 128.f) - mean1 * mean1 + 1e-5f);
        #pragma unroll
        for (int nt = 0; nt < 2; nt++) {
            int n = warp * 16 + nt * 8 + tig * 2;
            float g0 = ln1s[n], g1 = ln1s[n + 1];
            float bb0 = ln1b[n], bb1 = ln1b[n + 1];
            __half2 hv0 = __floats2half2_rn(
                (c3[nt][0] - mean0) * rstd0 * g0 + bb0,
                (c3[nt][1] - mean0) * rstd0 * g1 + bb1);
            __half2 hv1 = __floats2half2_rn(
                (c3[nt][2] - mean1) * rstd1 * g0 + bb0,
                (c3[nt][3] - mean1) * rstd1 * g1 + bb1);
            *reinterpret_cast<unsigned*>(&HN2[lr0][n]) = *reinterpret_cast<unsigned*>(&hv0);
            *reinterpret_cast<unsigned*>(&HN2[lr1][n]) = *reinterpret_cast<unsigned*>(&hv1);
        }

        // ---- stage 4: QKV GEMM of next layer (3 chunks, nt=2) ----
        __half (*WsA)[136] = reinterpret_cast<__half(*)[136]>(Wsraw);
        for (int chunk = 0; chunk < 3; chunk++) {
            __syncthreads();
            #pragma unroll
            for (int it = 0; it < 8; it++) {
                int idx = tid + it * 256;
                int r = idx >> 4, q = idx & 15;
                *reinterpret_cast<uint4*>(&WsA[r][q * 8]) = w4Reg[it];
            }
            __syncthreads();
            if (chunk + 1 < 3) {
                #pragma unroll
                for (int it = 0; it < 8; it++) {
                    int idx = tid + it * 256;
                    int r = idx >> 4, q = idx & 15;
                    w4Reg[it] = *reinterpret_cast<const uint4*>(
                        Win + (size_t)((chunk + 1) * 128 + r) * 128 + q * 8);
                }
            }
            float c4[2][4] = {};
            #pragma unroll
            for (int ks8 = 0; ks8 < 8; ks8++) {
                int kc = ks8 * 16;
                unsigned a[4];
                a[0] = *reinterpret_cast<const unsigned*>(&HN2[g    ][kc + tig * 2]);
                a[1] = *reinterpret_cast<const unsigned*>(&HN2[g + 8][kc + tig * 2]);
                a[2] = *reinterpret_cast<const unsigned*>(&HN2[g    ][kc + tig * 2 + 8]);
                a[3] = *reinterpret_cast<const unsigned*>(&HN2[g + 8][kc + tig * 2 + 8]);
                #pragma unroll
                for (int nt = 0; nt < 2; nt++) {
                    unsigned bfr[2];
                    int nrow = warp * 16 + nt * 8 + g;
                    bfr[0] = *reinterpret_cast<const unsigned*>(&WsA[nrow][kc + tig * 2]);
                    bfr[1] = *reinterpret_cast<const unsigned*>(&WsA[nrow][kc + tig * 2 + 8]);
                    mma16816(c4[nt], a, bfr);
                }
            }
            #pragma unroll
            for (int nt = 0; nt < 2; nt++) {
                int nl = warp * 16 + nt * 8 + tig * 2;
                int n = chunk * 128 + nl;
                float b0 = bin[n], b1v = bin[n + 1];
                float v00 = c4[nt][0] + b0, v01 = c4[nt][1] + b1v;
                float v10 = c4[nt][2] + b0, v11 = c4[nt][3] + b1v;
                if (chunk < 2) {
                    if (chunk == 0) { v00 *= QK_SCALE_L2E; v01 *= QK_SCALE_L2E;
                                      v10 *= QK_SCALE_L2E; v11 *= QK_SCALE_L2E; }
                    if (mrow0 < M) {
                        __half2 hv = __floats2half2_rn(v00, v01);
                        *reinterpret_cast<unsigned*>(qkvh + (size_t)mrow0 * 384 + n)
                            = *reinterpret_cast<unsigned*>(&hv);
                    }
                    if (mrow1 < M) {
                        __half2 hv = __floats2half2_rn(v10, v11);
                        *reinterpret_cast<unsigned*>(qkvh + (size_t)mrow1 * 384 + n)
                            = *reinterpret_cast<unsigned*>(&hv);
                    }
                } else {
                    int hh = nl >> 5, dd = nl & 31;
                    if (mrow0 < M) {
                        int bb = mrow0 / S_LEN, ss = mrow0 % S_LEN;
                        __half* vb = vT + ((size_t)(bb * N_HEADS + hh) * DHEAD + dd) * VT_PITCH + ss;
                        vb[0] = __float2half_rn(v00);
                        vb[VT_PITCH] = __float2half_rn(v01);
                    }
                    if (mrow1 < M) {
                        int bb = mrow1 / S_LEN, ss = mrow1 % S_LEN;
                        __half* vb = vT + ((size_t)(bb * N_HEADS + hh) * DHEAD + dd) * VT_PITCH + ss;
                        vb[0] = __float2half_rn(v10);
                        vb[VT_PITCH] = __float2half_rn(v11);
                    }
                }
            }
        }
    }
}

// ---------------- head ----------------
__global__ __launch_bounds__(64) void head_kernel(
    const float* __restrict__ h, const float* __restrict__ ls,
    const float* __restrict__ lb, const float* __restrict__ hw,
    const float* __restrict__ hb, float* __restrict__ out)
{
    int bidx = threadIdx.x >> 5;
    if (bidx >= BATCH) return;
    int lane = threadIdx.x & 31;
    const float* xr = h + (size_t)bidx * S_LEN * D_MODEL;
    float4 v = *reinterpret_cast<const float4*>(xr + lane * 4);
    float sum = v.x + v.y + v.z + v.w;
    #pragma unroll
    for (int o = 16; o; o >>= 1) sum += __shfl_xor_sync(0xffffffffu, sum, o);
    float mean = sum * (1.f / 128.f);
    float dx = v.x - mean, dy = v.y - mean, dz = v.z - mean, dw = v.w - mean;
    float vs = dx * dx + dy * dy + dz * dz + dw * dw;
    #pragma unroll
    for (int o = 16; o; o >>= 1) vs += __shfl_xor_sync(0xffffffffu, vs, o);
    float rstd = rsqrtf(vs * (1.f / 128.f) + 1e-5f);
    float4 s4 = *reinterpret_cast<const float4*>(ls + lane * 4);
    float4 b4 = *reinterpret_cast<const float4*>(lb + lane * 4);
    float4 w4 = *reinterpret_cast<const float4*>(hw + lane * 4);
    float dot = (dx * rstd * s4.x + b4.x) * w4.x
              + (dy * rstd * s4.y + b4.y) * w4.y
              + (dz * rstd * s4.z + b4.z) * w4.z
              + (dw * rstd * s4.w + b4.w) * w4.w;
    #pragma unroll
    for (int o = 16; o; o >>= 1) dot += __shfl_xor_sync(0xffffffffu, dot, o);
    if (lane == 0) out[bidx] = dot + hb[0];
}

// ---------------- launch ----------------
extern "C" void kernel_launch(void* const* d_in, const int* in_sizes, int n_in,
                              void* d_out, int out_size)
{
    const float* x        = (const float*)d_in[0];
    const float* embed_w  = (const float*)d_in[1];
    const float* embed_b  = (const float*)d_in[2];
    const float* pos_emb  = (const float*)d_in[3];
    const float* cls      = (const float*)d_in[4];
    const float* in_w     = (const float*)d_in[5];
    const float* in_b     = (const float*)d_in[6];
    const float* out_w    = (const float*)d_in[7];
    const float* out_b    = (const float*)d_in[8];
    const float* ln1_s    = (const float*)d_in[9];
    const float* ln1_b    = (const float*)d_in[10];
    const float* ln2_s    = (const float*)d_in[11];
    const float* ln2_b    = (const float*)d_in[12];
    const float* ff1_w    = (const float*)d_in[13];
    const float* ff1_b    = (const float*)d_in[14];
    const float* ff2_w    = (const float*)d_in[15];
    const float* ff2_b    = (const float*)d_in[16];
    const float* hln_s    = (const float*)d_in[17];
    const float* hln_b    = (const float*)d_in[18];
    const float* head_w   = (const float*)d_in[19];
    const float* head_b   = (const float*)d_in[20];
    float* outp = (float*)d_out;

    float *h, *po, *pl;
    __half *hnh, *qkvh, *vt, *wh;
    cudaGetSymbolAddress((void**)&h,     g_h);
    cudaGetSymbolAddress((void**)&hnh,   g_hnh);
    cudaGetSymbolAddress((void**)&qkvh,  g_qkvh);
    cudaGetSymbolAddress((void**)&vt,    g_vt);
    cudaGetSymbolAddress((void**)&po,    g_po);
    cudaGetSymbolAddress((void**)&pl,    g_pl);
    cudaGetSymbolAddress((void**)&wh,    g_wh);

    cudaFuncSetAttribute(mega_tail_kernel<true>,
                         cudaFuncAttributeMaxDynamicSharedMemorySize, SMEM_MEGA);
    cudaFuncSetAttribute(mega_tail_kernel<false>,
                         cudaFuncAttributeMaxDynamicSharedMemorySize, SMEM_MEGA);

    const int M = MROWS;
    const int MB128 = (M + 127) / 128;
    const int MB16  = (M + 15) / 16;   // 257
    const int QTILES = (S_LEN + BQ - 1) / BQ;

    convw_all_kernel<<<(CW_TOTAL + 255) / 256, 256>>>(in_w, out_w, ff1_w, ff2_w, wh);

    embed_ln_kernel<<<dim3(S_LEN, BATCH), 128>>>(
        x, embed_w, embed_b, pos_emb, cls, ln1_s, ln1_b, h, hnh);

    qkv_gemm_kernel<<<dim3(384 / 64, MB128), 256>>>(
        hnh, wh + WOFF_IN, in_b, qkvh, vt, M);

    for (int i = 0; i < NL; i++) {
        attn_kernel<<<dim3(QTILES * SPLITS, N_HEADS, BATCH), 256>>>(qkvh, vt, po, pl);
        if (i + 1 < NL) {
            mega_tail_kernel<true><<<MB16, 256, SMEM_MEGA>>>(
                po, pl,
                wh + WOFF_OUT + (size_t)i * 128 * 128, out_b + (size_t)i * 128,
                ln2_s + i * D_MODEL, ln2_b + i * D_MODEL,
                wh + WOFF_FF1 + (size_t)i * 512 * 128, ff1_b + (size_t)i * 512,
                wh + WOFF_FF2 + (size_t)i * 128 * 512, ff2_b + (size_t)i * 128,
                ln1_s + (i + 1) * D_MODEL, ln1_b + (i + 1) * D_MODEL,
                wh + WOFF_IN + (size_t)(i + 1) * 384 * 128, in_b + (size_t)(i + 1) * 384,
                h, qkvh, vt, M);
        } else {
            mega_tail_kernel<false><<<MB16, 256, SMEM_MEGA>>>(
                po, pl,
                wh + WOFF_OUT + (size_t)i * 128 * 128, out_b + (size_t)i * 128,
                ln2_s + i * D_MODEL, ln2_b + i * D_MODEL,
                wh + WOFF_FF1 + (size_t)i * 512 * 128, ff1_b + (size_t)i * 512,
                wh + WOFF_FF2 + (size_t)i * 128 * 512, ff2_b + (size_t)i * 128,
                nullptr, nullptr, nullptr, nullptr,
                h, nullptr, nullptr, M);
        }
    }

    head_kernel<<<1, 64>>>(h, hln_s, hln_b, head_w, head_b, outp);
}

// round 17
// speedup vs baseline: 1.0845x; 1.0845x over previous
#include <cuda_runtime.h>
#include <cuda_fp16.h>
#include <math.h>

#define NL 3
#define D_MODEL 128
#define N_HEADS 4
#define DHEAD 32
#define DFF 512
#define DIN 64
#define BATCH 2
#define LSEQ 2048
#define S_LEN 2049
#define MROWS (BATCH * S_LEN)   // 4098
// QK scale with log2(e) folded in: scores arrive in base-2 domain
#define QK_SCALE_L2E 0.25500526764086547f

#define SPLITS 3
#define KCHUNK 704
#define VT_PITCH 2112
#define PSTRIDE ((size_t)BATCH * N_HEADS * S_LEN)

// ---------------- scratch (device globals; no allocation) ----------------
__device__ float  g_h[MROWS * D_MODEL];
__device__ __half g_hnh[MROWS * D_MODEL];
__device__ __half g_qkvh[MROWS * 3 * D_MODEL];
__device__ __half g_vt[BATCH * N_HEADS * DHEAD * VT_PITCH];
__device__ float  g_po[SPLITS * BATCH * N_HEADS * S_LEN * DHEAD];
__device__ float  g_pl[SPLITS * BATCH * N_HEADS * S_LEN];
#define WOFF_IN  0
#define WOFF_OUT (NL * 384 * 128)
#define WOFF_FF1 (WOFF_OUT + NL * 128 * 128)
#define WOFF_FF2 (WOFF_FF1 + NL * 512 * 128)
#define WTOTAL   (WOFF_FF2 + NL * 128 * 512)
__device__ __half g_wh[WTOTAL];

#define CW_N0 (NL * 384 * 128 / 4)
#define CW_N1 (NL * 128 * 128 / 4)
#define CW_N2 (NL * 512 * 128 / 4)
#define CW_N3 (NL * 128 * 512 / 4)
#define CW_TOTAL (CW_N0 + CW_N1 + CW_N2 + CW_N3)

// ---------------- mega kernel dynamic smem layout (bytes) ----------------
#define OFF_ATTN 0                    // __half [32][136]  = 8704
#define OFF_HN2  8704                 // __half [32][136]  = 8704
#define OFF_HRES 17408                // float  [32][128]  = 16384
#define OFF_F    33792                // __half [32][520]  = 33280
#define OFF_WS   67072                // __half staging    = 40960
#define OFF_PS   108032               // float  [32][4]    = 512
#define OFF_PQ   108544               // float  [32][4]    = 512
#define SMEM_MEGA 109056

// ---------------- mma helper ----------------
__device__ __forceinline__ void mma16816(
    float c[4], const unsigned a[4], const unsigned b[2])
{
    asm volatile(
        "mma.sync.aligned.m16n8k16.row.col.f32.f16.f16.f32 "
        "{%0,%1,%2,%3}, {%4,%5,%6,%7}, {%8,%9}, {%0,%1,%2,%3};\n"
        : "+f"(c[0]), "+f"(c[1]), "+f"(c[2]), "+f"(c[3])
        : "r"(a[0]), "r"(a[1]), "r"(a[2]), "r"(a[3]),
          "r"(b[0]), "r"(b[1]));
}

// ---------------- fused weight fp32 -> fp16 conversion ----------------
__global__ __launch_bounds__(256) void convw_all_kernel(
    const float* __restrict__ s0, const float* __restrict__ s1,
    const float* __restrict__ s2, const float* __restrict__ s3,
    __half* __restrict__ dst)
{
    int i = blockIdx.x * 256 + threadIdx.x;
    if (i >= CW_TOTAL) return;
    const float* src;
    int off, local = i;
    if (local < CW_N0)                { src = s0; off = WOFF_IN; }
    else if ((local -= CW_N0) < CW_N1){ src = s1; off = WOFF_OUT; }
    else if ((local -= CW_N1) < CW_N2){ src = s2; off = WOFF_FF1; }
    else { local -= CW_N2;              src = s3; off = WOFF_FF2; }
    float4 v = *reinterpret_cast<const float4*>(src + (size_t)local * 4);
    __half2 a = __floats2half2_rn(v.x, v.y);
    __half2 b = __floats2half2_rn(v.z, v.w);
    uint2 pk;
    pk.x = *reinterpret_cast<unsigned*>(&a);
    pk.y = *reinterpret_cast<unsigned*>(&b);
    *reinterpret_cast<uint2*>(dst + (size_t)off + (size_t)local * 4) = pk;
}

// ---------------- embedding + fused LN1(layer0) ----------------
__global__ __launch_bounds__(128) void embed_ln_kernel(
    const float* __restrict__ x, const float* __restrict__ ew,
    const float* __restrict__ eb, const float* __restrict__ pos,
    const float* __restrict__ cls, const float* __restrict__ lns,
    const float* __restrict__ lnb, float* __restrict__ h,
    __half* __restrict__ hn)
{
    __shared__ float xs[DIN];
    __shared__ float red[8];
    int s = blockIdx.x, b = blockIdx.y;
    int d = threadIdx.x;
    if (s > 0 && d < DIN) xs[d] = x[((size_t)b * LSEQ + (s - 1)) * DIN + d];
    __syncthreads();
    float val;
    if (s == 0) {
        val = cls[d] + pos[d];
    } else {
        float acc = 0.f;
        const float* wr = ew + (size_t)d * DIN;
        #pragma unroll
        for (int j = 0; j < DIN; j++) acc = fmaf(xs[j], wr[j], acc);
        val = acc + eb[d] + pos[(size_t)s * D_MODEL + d];
    }
    size_t row = (size_t)b * S_LEN + s;
    h[row * D_MODEL + d] = val;
    int w = d >> 5, lane = d & 31;
    float sv = val, qv = val * val;
    #pragma unroll
    for (int o = 16; o; o >>= 1) {
        sv += __shfl_xor_sync(0xffffffffu, sv, o);
        qv += __shfl_xor_sync(0xffffffffu, qv, o);
    }
    if (lane == 0) { red[w] = sv; red[4 + w] = qv; }
    __syncthreads();
    float sum = red[0] + red[1] + red[2] + red[3];
    float sq  = red[4] + red[5] + red[6] + red[7];
    float mean = sum * (1.f / 128.f);
    float rstd = rsqrtf(sq * (1.f / 128.f) - mean * mean + 1e-5f);
    hn[row * D_MODEL + d] = __float2half_rn((val - mean) * rstd * lns[d] + lnb[d]);
}

// ---------------- QKV tensor-core GEMM (layer 0 only) ----------------
#define GPITCH 40
__global__ __launch_bounds__(256) void qkv_gemm_kernel(
    const __half* __restrict__ A, const __half* __restrict__ W,
    const float* __restrict__ bias, __half* __restrict__ C,
    __half* __restrict__ vT, int M)
{
    const int N = 384, K = 128;
    __shared__ __half As[128][GPITCH];
    __shared__ __half Ws[64][GPITCH];
    const int tid = threadIdx.x;
    const int warp = tid >> 5;
    const int lane = tid & 31;
    const int g = lane >> 2;
    const int tig = lane & 3;
    const int warp_m = warp >> 1;
    const int warp_n = warp & 1;
    const int m0 = blockIdx.y * 128;
    const int n0 = blockIdx.x * 64;
    const int NK = K / 32;
    const int wr = tid >> 2, wq = tid & 3;

    float c[2][4][4] = {};

    uint4 aReg[2], wReg;
    #pragma unroll
    for (int it = 0; it < 2; it++) {
        int idx = tid + it * 256;
        int r = idx >> 2, quad = idx & 3;
        int m = m0 + r;
        aReg[it] = (m < M)
            ? *reinterpret_cast<const uint4*>(A + (size_t)m * K + quad * 8)
            : make_uint4(0u, 0u, 0u, 0u);
    }
    wReg = *reinterpret_cast<const uint4*>(W + (size_t)(n0 + wr) * K + wq * 8);

    for (int kt = 0; kt < NK; kt++) {
        #pragma unroll
        for (int it = 0; it < 2; it++) {
            int idx = tid + it * 256;
            int r = idx >> 2, quad = idx & 3;
            *reinterpret_cast<uint4*>(&As[r][quad * 8]) = aReg[it];
        }
        *reinterpret_cast<uint4*>(&Ws[wr][wq * 8]) = wReg;
        __syncthreads();
        if (kt + 1 < NK) {
            int k0 = (kt + 1) * 32;
            #pragma unroll
            for (int it = 0; it < 2; it++) {
                int idx = tid + it * 256;
                int r = idx >> 2, quad = idx & 3;
                int m = m0 + r;
                aReg[it] = (m < M)
                    ? *reinterpret_cast<const uint4*>(A + (size_t)m * K + k0 + quad * 8)
                    : make_uint4(0u, 0u, 0u, 0u);
            }
            wReg = *reinterpret_cast<const uint4*>(W + (size_t)(n0 + wr) * K + k0 + wq * 8);
        }
        #pragma unroll
        for (int ks = 0; ks < 2; ks++) {
            unsigned a[2][4];
            #pragma unroll
            for (int mt = 0; mt < 2; mt++) {
                int rbase = warp_m * 32 + mt * 16;
                a[mt][0] = *reinterpret_cast<const unsigned*>(&As[rbase + g    ][ks * 16 + tig * 2]);
                a[mt][1] = *reinterpret_cast<const unsigned*>(&As[rbase + g + 8][ks * 16 + tig * 2]);
                a[mt][2] = *reinterpret_cast<const unsigned*>(&As[rbase + g    ][ks * 16 + tig * 2 + 8]);
                a[mt][3] = *reinterpret_cast<const unsigned*>(&As[rbase + g + 8][ks * 16 + tig * 2 + 8]);
            }
            #pragma unroll
            for (int nt = 0; nt < 4; nt++) {
                unsigned bfr[2];
                int nrow = warp_n * 32 + nt * 8 + g;
                bfr[0] = *reinterpret_cast<const unsigned*>(&Ws[nrow][ks * 16 + tig * 2]);
                bfr[1] = *reinterpret_cast<const unsigned*>(&Ws[nrow][ks * 16 + tig * 2 + 8]);
                mma16816(c[0][nt], a[0], bfr);
                mma16816(c[1][nt], a[1], bfr);
            }
        }
        __syncthreads();
    }

    #pragma unroll
    for (int mt = 0; mt < 2; mt++) {
        #pragma unroll
        for (int half_row = 0; half_row < 2; half_row++) {
            int m = m0 + warp_m * 32 + mt * 16 + g + half_row * 8;
            if (m >= M) continue;
            int bb = m / S_LEN, ss = m % S_LEN;
            #pragma unroll
            for (int nt = 0; nt < 4; nt++) {
                int n = n0 + warp_n * 32 + nt * 8 + tig * 2;
                float v0 = c[mt][nt][half_row * 2 + 0] + bias[n];
                float v1 = c[mt][nt][half_row * 2 + 1] + bias[n + 1];
                if (n >= 256) {
                    int hh = (n - 256) >> 5, dd = (n - 256) & 31;
                    __half* vbase = vT + ((size_t)(bb * N_HEADS + hh) * DHEAD + dd) * VT_PITCH + ss;
                    vbase[0] = __float2half_rn(v0);
                    vbase[VT_PITCH] = __float2half_rn(v1);
                } else {
                    if (n < 128) { v0 *= QK_SCALE_L2E; v1 *= QK_SCALE_L2E; }
                    __half2 hv = __floats2half2_rn(v0, v1);
                    *reinterpret_cast<unsigned*>(
                        C + (size_t)m * N + n) = *reinterpret_cast<unsigned*>(&hv);
                }
            }
        }
    }
}

// ---------------- split-S flash attention (base-2 exp; l via ones-MMA) ---
#define BQ 128
#define BK 64
#define QPITCH 40
#define VPITCH 72
#define VROWS 40   // 32 V dims + 8 extra rows (row 32 = ones, 33-39 = zero)

__global__ __launch_bounds__(256, 3) void attn_kernel(
    const __half* __restrict__ qkv, const __half* __restrict__ vT,
    float* __restrict__ po, float* __restrict__ pl)
{
    __shared__ __half Qs[BQ][QPITCH];
    __shared__ __half Kt[2][BK][QPITCH];
    __shared__ __half Vt[2][VROWS][VPITCH];
    const int tid = threadIdx.x;
    const int warp = tid >> 5;
    const int lane = tid & 31;
    const int g = lane >> 2;
    const int tig = lane & 3;
    const int b = blockIdx.z, h = blockIdx.y;
    const int tile = blockIdx.x / SPLITS;
    const int split = blockIdx.x % SPLITS;
    const int q0 = tile * BQ;
    const int qbase = warp * 16;
    const int kstart = split * KCHUNK;
    const int kend = min(kstart + KCHUNK, S_LEN);
    const int ntile = (kend - kstart + BK - 1) / BK;

    // ---- Q tile ----
    #pragma unroll
    for (int idx = tid; idx < BQ * 4; idx += 256) {
        int r = idx >> 2, quad = idx & 3;
        int q = q0 + r;
        uint4 v = make_uint4(0u, 0u, 0u, 0u);
        if (q < S_LEN)
            v = *reinterpret_cast<const uint4*>(
                qkv + ((size_t)(b * S_LEN + q)) * 384 + h * 32 + quad * 8);
        *reinterpret_cast<uint4*>(&Qs[r][quad * 8]) = v;
    }
    // ---- ones/zero rows of Vt (both buffers, rows 32..39): set once ----
    // 2 bufs * 8 rows * 9 uint4-groups (72 halfs/row) = 144 slots
    for (int idx = tid; idx < 2 * 8 * 9; idx += 256) {
        int bufp = idx / 72;
        int rem = idx % 72;
        int rr = 32 + rem / 9;
        int qq = rem % 9;
        unsigned pat = (rr == 32) ? 0x3C003C00u : 0u;   // half2(1,1) : 0
        *reinterpret_cast<uint4*>(&Vt[bufp][rr][qq * 8]) =
            make_uint4(pat, pat, pat, pat);
    }

    const __half* Kbase = qkv + (size_t)b * S_LEN * 384 + 128 + h * 32;
    const __half* Vbase = vT + (size_t)(b * N_HEADS + h) * DHEAD * VT_PITCH;
    const int kr = tid >> 2, kq = tid & 3;
    const int vr = tid >> 3, vq = tid & 7;

    uint4 kreg, vreg;
    {
        int kg = kstart + kr;
        kreg = (kg < S_LEN)
            ? *reinterpret_cast<const uint4*>(Kbase + (size_t)kg * 384 + kq * 8)
            : make_uint4(0u, 0u, 0u, 0u);
        vreg = *reinterpret_cast<const uint4*>(Vbase + (size_t)vr * VT_PITCH + kstart + vq * 8);
    }
    *reinterpret_cast<uint4*>(&Kt[0][kr][kq * 8]) = kreg;
    *reinterpret_cast<uint4*>(&Vt[0][vr][vq * 8]) = vreg;
    __syncthreads();

    unsigned A[2][4];
    #pragma unroll
    for (int ks = 0; ks < 2; ks++) {
        A[ks][0] = *reinterpret_cast<const unsigned*>(&Qs[qbase + g    ][ks * 16 + tig * 2]);
        A[ks][1] = *reinterpret_cast<const unsigned*>(&Qs[qbase + g + 8][ks * 16 + tig * 2]);
        A[ks][2] = *reinterpret_cast<const unsigned*>(&Qs[qbase + g    ][ks * 16 + tig * 2 + 8]);
        A[ks][3] = *reinterpret_cast<const unsigned*>(&Qs[qbase + g + 8][ks * 16 + tig * 2 + 8]);
    }

    float o[4][4] = {};
    float o4[4] = {};   // ones-column tile: row-sums of P (l values)

    for (int t = 0; t < ntile; t++) {
        const int kb = kstart + t * BK;
        const int buf = t & 1;
        if (t + 1 < ntile) {
            int kb2 = kb + BK;
            int kg = kb2 + kr;
            kreg = (kg < S_LEN)
                ? *reinterpret_cast<const uint4*>(Kbase + (size_t)kg * 384 + kq * 8)
                : make_uint4(0u, 0u, 0u, 0u);
            vreg = *reinterpret_cast<const uint4*>(Vbase + (size_t)vr * VT_PITCH + kb2 + vq * 8);
        }

        float s[8][4];
        #pragma unroll
        for (int j = 0; j < 8; j++) {
            s[j][0] = s[j][1] = s[j][2] = s[j][3] = 0.f;
            #pragma unroll
            for (int ks = 0; ks < 2; ks++) {
                unsigned bfr[2];
                bfr[0] = *reinterpret_cast<const unsigned*>(&Kt[buf][j * 8 + g][ks * 16 + tig * 2]);
                bfr[1] = *reinterpret_cast<const unsigned*>(&Kt[buf][j * 8 + g][ks * 16 + tig * 2 + 8]);
                mma16816(s[j], A[ks], bfr);
            }
        }
        if (kb + BK > S_LEN) {
            #pragma unroll
            for (int j = 0; j < 8; j++) {
                int key = kb + j * 8 + tig * 2;
                if (key >= S_LEN)     { s[j][0] = -1e30f; s[j][2] = -1e30f; }
                if (key + 1 >= S_LEN) { s[j][1] = -1e30f; s[j][3] = -1e30f; }
            }
        }

        // base-2 fixed-max softmax: p = exp2(s); l comes from the ones-MMA
        unsigned ph[8][2];
        #pragma unroll
        for (int j = 0; j < 8; j++) {
            __half2 h2a = __floats2half2_rn(exp2f(s[j][0]), exp2f(s[j][1]));
            __half2 h2b = __floats2half2_rn(exp2f(s[j][2]), exp2f(s[j][3]));
            ph[j][0] = *reinterpret_cast<unsigned*>(&h2a);
            ph[j][1] = *reinterpret_cast<unsigned*>(&h2b);
        }

        #pragma unroll
        for (int kt = 0; kt < 4; kt++) {
            unsigned pa[4] = { ph[2 * kt][0], ph[2 * kt][1],
                               ph[2 * kt + 1][0], ph[2 * kt + 1][1] };
            #pragma unroll
            for (int nt = 0; nt < 4; nt++) {
                unsigned bfr[2];
                bfr[0] = *reinterpret_cast<const unsigned*>(&Vt[buf][nt * 8 + g][kt * 16 + tig * 2]);
                bfr[1] = *reinterpret_cast<const unsigned*>(&Vt[buf][nt * 8 + g][kt * 16 + tig * 2 + 8]);
                mma16816(o[nt], pa, bfr);
            }
            // ones tile (rows 32..39): accumulates row-sums into column 32
            {
                unsigned bfr[2];
                bfr[0] = *reinterpret_cast<const unsigned*>(&Vt[buf][32 + g][kt * 16 + tig * 2]);
                bfr[1] = *reinterpret_cast<const unsigned*>(&Vt[buf][32 + g][kt * 16 + tig * 2 + 8]);
                mma16816(o4, pa, bfr);
            }
        }
        if (t + 1 < ntile) {
            *reinterpret_cast<uint4*>(&Kt[buf ^ 1][kr][kq * 8]) = kreg;
            *reinterpret_cast<uint4*>(&Vt[buf ^ 1][vr][vq * 8]) = vreg;
        }
        __syncthreads();
    }

    // l lives in column 32 of the ones tile: thread tig==0 holds it
    // (o4[0] = row g, o4[2] = row g+8) — exactly the pl writers.
    const size_t pbase = (((size_t)split * BATCH + b) * N_HEADS + h) * S_LEN;
    int qa = q0 + qbase + g;
    int qb2 = qa + 8;
    if (qa < S_LEN) {
        #pragma unroll
        for (int nt = 0; nt < 4; nt++) {
            float2 v = make_float2(o[nt][0], o[nt][1]);
            *reinterpret_cast<float2*>(po + (pbase + qa) * DHEAD + nt * 8 + tig * 2) = v;
        }
        if (tig == 0) pl[pbase + qa] = o4[0];
    }
    if (qb2 < S_LEN) {
        #pragma unroll
        for (int nt = 0; nt < 4; nt++) {
            float2 v = make_float2(o[nt][2], o[nt][3]);
            *reinterpret_cast<float2*>(po + (pbase + qb2) * DHEAD + nt * 8 + tig * 2) = v;
        }
        if (tig == 0) pl[pbase + qb2] = o4[2];
    }
}

// ---------------- MEGA layer-tail kernel (256 thr, R15 version) ----------
template <bool QKV_NEXT>
__global__ __launch_bounds__(256) void mega_tail_kernel(
    const float* __restrict__ po, const float* __restrict__ pl,
    const __half* __restrict__ Wout, const float* __restrict__ bout,
    const float* __restrict__ ln2s, const float* __restrict__ ln2b,
    const __half* __restrict__ W1, const float* __restrict__ b1,
    const __half* __restrict__ W2, const float* __restrict__ b2,
    const float* __restrict__ ln1s, const float* __restrict__ ln1b,
    const __half* __restrict__ Win, const float* __restrict__ bin,
    float* __restrict__ h, __half* __restrict__ qkvh,
    __half* __restrict__ vT, int M)
{
    extern __shared__ char smem[];
    __half (*Attn)[136] = reinterpret_cast<__half(*)[136]>(smem + OFF_ATTN);
    __half (*HN2)[136]  = reinterpret_cast<__half(*)[136]>(smem + OFF_HN2);
    float (*Hres)[128]  = reinterpret_cast<float(*)[128]>(smem + OFF_HRES);
    __half (*F)[520]    = reinterpret_cast<__half(*)[520]>(smem + OFF_F);
    __half* Wsraw       = reinterpret_cast<__half*>(smem + OFF_WS);
    float (*psum)[4]    = reinterpret_cast<float(*)[4]>(smem + OFF_PS);
    float (*psq)[4]     = reinterpret_cast<float(*)[4]>(smem + OFF_PQ);

    const int tid = threadIdx.x;
    const int warp = tid >> 5;
    const int lane = tid & 31;
    const int g = lane >> 2;
    const int tig = lane & 3;
    const int warp_m = warp >> 2;
    const int warp_n = warp & 3;
    const int m0 = blockIdx.x * 32;

    {
        __half (*WsA)[136] = reinterpret_cast<__half(*)[136]>(Wsraw);
        #pragma unroll
        for (int it = 0; it < 8; it++) {
            int idx = tid + it * 256;
            int r = idx >> 4, q = idx & 15;
            *reinterpret_cast<uint4*>(&WsA[r][q * 8]) =
                *reinterpret_cast<const uint4*>(Wout + (size_t)r * 128 + q * 8);
        }
    }

    {
        int row = tid >> 3;
        int dseg = (tid & 7) * 16;
        int mrow = m0 + row;
        if (mrow < M) {
            int bb = mrow / S_LEN, qq = mrow % S_LEN;
            int hh = dseg >> 5, dd = dseg & 31;
            size_t prow = ((size_t)bb * N_HEADS + hh) * S_LEN + qq;
            float linv = 1.f / (pl[prow] + pl[prow + PSTRIDE] + pl[prow + 2 * PSTRIDE]);
            float acc[16];
            #pragma unroll
            for (int t = 0; t < 4; t++) {
                float4 p0 = *reinterpret_cast<const float4*>(po + prow * DHEAD + dd + t * 4);
                float4 p1 = *reinterpret_cast<const float4*>(po + (prow + PSTRIDE) * DHEAD + dd + t * 4);
                float4 p2 = *reinterpret_cast<const float4*>(po + (prow + 2 * PSTRIDE) * DHEAD + dd + t * 4);
                acc[t * 4 + 0] = (p0.x + p1.x + p2.x) * linv;
                acc[t * 4 + 1] = (p0.y + p1.y + p2.y) * linv;
                acc[t * 4 + 2] = (p0.z + p1.z + p2.z) * linv;
                acc[t * 4 + 3] = (p0.w + p1.w + p2.w) * linv;
            }
            unsigned pk[8];
            #pragma unroll
            for (int t = 0; t < 8; t++) {
                __half2 hv = __floats2half2_rn(acc[t * 2], acc[t * 2 + 1]);
                pk[t] = *reinterpret_cast<unsigned*>(&hv);
            }
            *reinterpret_cast<uint4*>(&Attn[row][dseg]) = make_uint4(pk[0], pk[1], pk[2], pk[3]);
            *reinterpret_cast<uint4*>(&Attn[row][dseg + 8]) = make_uint4(pk[4], pk[5], pk[6], pk[7]);
            #pragma unroll
            for (int t = 0; t < 4; t++)
                *reinterpret_cast<float4*>(&Hres[row][dseg + t * 4]) =
                    *reinterpret_cast<const float4*>(h + (size_t)mrow * 128 + dseg + t * 4);
        } else {
            uint4 z = make_uint4(0u, 0u, 0u, 0u);
            *reinterpret_cast<uint4*>(&Attn[row][dseg]) = z;
            *reinterpret_cast<uint4*>(&Attn[row][dseg + 8]) = z;
            float4 fz = make_float4(0.f, 0.f, 0.f, 0.f);
            #pragma unroll
            for (int t = 0; t < 4; t++)
                *reinterpret_cast<float4*>(&Hres[row][dseg + t * 4]) = fz;
        }
    }
    __syncthreads();

    float c1[4][4] = {};
    {
        __half (*WsA)[136] = reinterpret_cast<__half(*)[136]>(Wsraw);
        #pragma unroll
        for (int ks8 = 0; ks8 < 8; ks8++) {
            int kc = ks8 * 16;
            unsigned a[4];
            int rbase = warp_m * 16;
            a[0] = *reinterpret_cast<const unsigned*>(&Attn[rbase + g    ][kc + tig * 2]);
            a[1] = *reinterpret_cast<const unsigned*>(&Attn[rbase + g + 8][kc + tig * 2]);
            a[2] = *reinterpret_cast<const unsigned*>(&Attn[rbase + g    ][kc + tig * 2 + 8]);
            a[3] = *reinterpret_cast<const unsigned*>(&Attn[rbase + g + 8][kc + tig * 2 + 8]);
            #pragma unroll
            for (int nt = 0; nt < 4; nt++) {
                unsigned bfr[2];
                int nrow = warp_n * 32 + nt * 8 + g;
                bfr[0] = *reinterpret_cast<const unsigned*>(&WsA[nrow][kc + tig * 2]);
                bfr[1] = *reinterpret_cast<const unsigned*>(&WsA[nrow][kc + tig * 2 + 8]);
                mma16816(c1[nt], a, bfr);
            }
        }
    }

    uint4 w1Reg[8];
    #pragma unroll
    for (int it = 0; it < 8; it++) {
        int idx = tid + it * 256;
        int r = idx >> 2, q = idx & 3;
        w1Reg[it] = *reinterpret_cast<const uint4*>(W1 + (size_t)r * 128 + q * 8);
    }

    const int lr0 = warp_m * 16 + g, lr1 = lr0 + 8;
    #pragma unroll
    for (int nt = 0; nt < 4; nt++) {
        int n = warp_n * 32 + nt * 8 + tig * 2;
        float b0 = bout[n], b1v = bout[n + 1];
        c1[nt][0] += b0 + Hres[lr0][n];
        c1[nt][1] += b1v + Hres[lr0][n + 1];
        c1[nt][2] += b0 + Hres[lr1][n];
        c1[nt][3] += b1v + Hres[lr1][n + 1];
    }
    {
        float s0 = 0.f, q0 = 0.f, s1 = 0.f, q1 = 0.f;
        #pragma unroll
        for (int nt = 0; nt < 4; nt++) {
            s0 += c1[nt][0] + c1[nt][1];
            q0 += c1[nt][0] * c1[nt][0] + c1[nt][1] * c1[nt][1];
            s1 += c1[nt][2] + c1[nt][3];
            q1 += c1[nt][2] * c1[nt][2] + c1[nt][3] * c1[nt][3];
        }
        #pragma unroll
        for (int o = 1; o < 4; o <<= 1) {
            s0 += __shfl_xor_sync(0xffffffffu, s0, o);
            q0 += __shfl_xor_sync(0xffffffffu, q0, o);
            s1 += __shfl_xor_sync(0xffffffffu, s1, o);
            q1 += __shfl_xor_sync(0xffffffffu, q1, o);
        }
        if (tig == 0) {
            psum[lr0][warp_n] = s0; psq[lr0][warp_n] = q0;
            psum[lr1][warp_n] = s1; psq[lr1][warp_n] = q1;
        }
        __syncthreads();
        float sum0 = psum[lr0][0] + psum[lr0][1] + psum[lr0][2] + psum[lr0][3];
        float sq0  = psq[lr0][0] + psq[lr0][1] + psq[lr0][2] + psq[lr0][3];
        float sum1 = psum[lr1][0] + psum[lr1][1] + psum[lr1][2] + psum[lr1][3];
        float sq1  = psq[lr1][0] + psq[lr1][1] + psq[lr1][2] + psq[lr1][3];
        float mean0 = sum0 * (1.f / 128.f);
        float rstd0 = rsqrtf(sq0 * (1.f / 128.f) - mean0 * mean0 + 1e-5f);
        float mean1 = sum1 * (1.f / 128.f);
        float rstd1 = rsqrtf(sq1 * (1.f / 128.f) - mean1 * mean1 + 1e-5f);
        #pragma unroll
        for (int nt = 0; nt < 4; nt++) {
            int n = warp_n * 32 + nt * 8 + tig * 2;
            float g0 = ln2s[n], g1 = ln2s[n + 1];
            float bb0 = ln2b[n], bb1 = ln2b[n + 1];
            __half2 hv0 = __floats2half2_rn(
                (c1[nt][0] - mean0) * rstd0 * g0 + bb0,
                (c1[nt][1] - mean0) * rstd0 * g1 + bb1);
            __half2 hv1 = __floats2half2_rn(
                (c1[nt][2] - mean1) * rstd1 * g0 + bb0,
                (c1[nt][3] - mean1) * rstd1 * g1 + bb1);
            *reinterpret_cast<unsigned*>(&HN2[lr0][n]) = *reinterpret_cast<unsigned*>(&hv0);
            *reinterpret_cast<unsigned*>(&HN2[lr1][n]) = *reinterpret_cast<unsigned*>(&hv1);
            Hres[lr0][n] = c1[nt][0]; Hres[lr0][n + 1] = c1[nt][1];
            Hres[lr1][n] = c1[nt][2]; Hres[lr1][n + 1] = c1[nt][3];
        }
    }

    float c2[2][8][4] = {};
    {
        __half (*WsB)[40] = reinterpret_cast<__half(*)[40]>(Wsraw);
        #pragma unroll
        for (int kt = 0; kt < 4; kt++) {
            __syncthreads();
            #pragma unroll
            for (int it = 0; it < 8; it++) {
                int idx = tid + it * 256;
                int r = idx >> 2, q = idx & 3;
                *reinterpret_cast<uint4*>(&WsB[r][q * 8]) = w1Reg[it];
            }
            __syncthreads();
            if (kt + 1 < 4) {
                int k0 = (kt + 1) * 32;
                #pragma unroll
                for (int it = 0; it < 8; it++) {
                    int idx = tid + it * 256;
                    int r = idx >> 2, q = idx & 3;
                    w1Reg[it] = *reinterpret_cast<const uint4*>(
                        W1 + (size_t)r * 128 + k0 + q * 8);
                }
            }
            #pragma unroll
            for (int ks = 0; ks < 2; ks++) {
                int kc = kt * 32 + ks * 16;
                unsigned a0[4], a1[4];
                a0[0] = *reinterpret_cast<const unsigned*>(&HN2[g     ][kc + tig * 2]);
                a0[1] = *reinterpret_cast<const unsigned*>(&HN2[g + 8 ][kc + tig * 2]);
                a0[2] = *reinterpret_cast<const unsigned*>(&HN2[g     ][kc + tig * 2 + 8]);
                a0[3] = *reinterpret_cast<const unsigned*>(&HN2[g + 8 ][kc + tig * 2 + 8]);
                a1[0] = *reinterpret_cast<const unsigned*>(&HN2[g + 16][kc + tig * 2]);
                a1[1] = *reinterpret_cast<const unsigned*>(&HN2[g + 24][kc + tig * 2]);
                a1[2] = *reinterpret_cast<const unsigned*>(&HN2[g + 16][kc + tig * 2 + 8]);
                a1[3] = *reinterpret_cast<const unsigned*>(&HN2[g + 24][kc + tig * 2 + 8]);
                #pragma unroll
                for (int nt = 0; nt < 8; nt++) {
                    unsigned bfr[2];
                    int nrow = warp * 64 + nt * 8 + g;
                    bfr[0] = *reinterpret_cast<const unsigned*>(&WsB[nrow][ks * 16 + tig * 2]);
                    bfr[1] = *reinterpret_cast<const unsigned*>(&WsB[nrow][ks * 16 + tig * 2 + 8]);
                    mma16816(c2[0][nt], a0, bfr);
                    mma16816(c2[1][nt], a1, bfr);
                }
            }
        }
    }

    uint4 w2Reg[4];
    #pragma unroll
    for (int it = 0; it < 4; it++) {
        int idx = tid + it * 256;
        int r = idx >> 3, q = idx & 7;
        w2Reg[it] = *reinterpret_cast<const uint4*>(W2 + (size_t)r * 512 + q * 8);
    }

    #pragma unroll
    for (int mt = 0; mt < 2; mt++) {
        #pragma unroll
        for (int hr = 0; hr < 2; hr++) {
            int lr = mt * 16 + hr * 8 + g;
            #pragma unroll
            for (int nt = 0; nt < 8; nt++) {
                int n = warp * 64 + nt * 8 + tig * 2;
                float v0 = fmaxf(c2[mt][nt][hr * 2 + 0] + b1[n], 0.f);
                float v1 = fmaxf(c2[mt][nt][hr * 2 + 1] + b1[n + 1], 0.f);
                __half2 hv = __floats2half2_rn(v0, v1);
                *reinterpret_cast<unsigned*>(&F[lr][n]) = *reinterpret_cast<unsigned*>(&hv);
            }
        }
    }

    float c3[4][4] = {};
    {
        __half (*WsC)[128][72] = reinterpret_cast<__half(*)[128][72]>(Wsraw);
        __syncthreads();
        #pragma unroll
        for (int it = 0; it < 4; it++) {
            int idx = tid + it * 256;
            int r = idx >> 3, q = idx & 7;
            *reinterpret_cast<uint4*>(&WsC[0][r][q * 8]) = w2Reg[it];
        }
        __syncthreads();
        #pragma unroll
        for (int kt = 0; kt < 8; kt++) {
            const int buf = kt & 1;
            if (kt + 1 < 8) {
                int k0 = (kt + 1) * 64;
                #pragma unroll
                for (int it = 0; it < 4; it++) {
                    int idx = tid + it * 256;
                    int r = idx >> 3, q = idx & 7;
                    uint4 wv = *reinterpret_cast<const uint4*>(
                        W2 + (size_t)r * 512 + k0 + q * 8);
                    *reinterpret_cast<uint4*>(&WsC[buf ^ 1][r][q * 8]) = wv;
                }
            }
            #pragma unroll
            for (int ks = 0; ks < 4; ks++) {
                int kc = kt * 64 + ks * 16;
                unsigned a[4];
                int rbase = warp_m * 16;
                a[0] = *reinterpret_cast<const unsigned*>(&F[rbase + g    ][kc + tig * 2]);
                a[1] = *reinterpret_cast<const unsigned*>(&F[rbase + g + 8][kc + tig * 2]);
                a[2] = *reinterpret_cast<const unsigned*>(&F[rbase + g    ][kc + tig * 2 + 8]);
                a[3] = *reinterpret_cast<const unsigned*>(&F[rbase + g + 8][kc + tig * 2 + 8]);
                #pragma unroll
                for (int nt = 0; nt < 4; nt++) {
                    unsigned bfr[2];
                    int nrow = warp_n * 32 + nt * 8 + g;
                    bfr[0] = *reinterpret_cast<const unsigned*>(&WsC[buf][nrow][ks * 16 + tig * 2]);
                    bfr[1] = *reinterpret_cast<const unsigned*>(&WsC[buf][nrow][ks * 16 + tig * 2 + 8]);
                    mma16816(c3[nt], a, bfr);
                }
            }
            __syncthreads();
        }
    }

    uint4 w4Reg[8];
    if (QKV_NEXT) {
        #pragma unroll
        for (int it = 0; it < 8; it++) {
            int idx = tid + it * 256;
            int r = idx >> 4, q = idx & 15;
            w4Reg[it] = *reinterpret_cast<const uint4*>(Win + (size_t)r * 128 + q * 8);
        }
    }

    const int mrow0 = m0 + lr0, mrow1 = m0 + lr1;
    #pragma unroll
    for (int nt = 0; nt < 4; nt++) {
        int n = warp_n * 32 + nt * 8 + tig * 2;
        float b0 = b2[n], b1v = b2[n + 1];
        c3[nt][0] += b0 + Hres[lr0][n];
        c3[nt][1] += b1v + Hres[lr0][n + 1];
        c3[nt][2] += b0 + Hres[lr1][n];
        c3[nt][3] += b1v + Hres[lr1][n + 1];
        if (mrow0 < M)
            *reinterpret_cast<float2*>(h + (size_t)mrow0 * 128 + n) =
                make_float2(c3[nt][0], c3[nt][1]);
        if (mrow1 < M)
            *reinterpret_cast<float2*>(h + (size_t)mrow1 * 128 + n) =
                make_float2(c3[nt][2], c3[nt][3]);
    }

    if (QKV_NEXT) {
        float s0 = 0.f, q0 = 0.f, s1 = 0.f, q1 = 0.f;
        #pragma unroll
        for (int nt = 0; nt < 4; nt++) {
            s0 += c3[nt][0] + c3[nt][1];
            q0 += c3[nt][0] * c3[nt][0] + c3[nt][1] * c3[nt][1];
            s1 += c3[nt][2] + c3[nt][3];
            q1 += c3[nt][2] * c3[nt][2] + c3[nt][3] * c3[nt][3];
        }
        #pragma unroll
        for (int o = 1; o < 4; o <<= 1) {
            s0 += __shfl_xor_sync(0xffffffffu, s0, o);
            q0 += __shfl_xor_sync(0xffffffffu, q0, o);
            s1 += __shfl_xor_sync(0xffffffffu, s1, o);
            q1 += __shfl_xor_sync(0xffffffffu, q1, o);
        }
        __syncthreads();
        if (tig == 0) {
            psum[lr0][warp_n] = s0; psq[lr0][warp_n] = q0;
            psum[lr1][warp_n] = s1; psq[lr1][warp_n] = q1;
        }
        __syncthreads();
        float sum0 = psum[lr0][0] + psum[lr0][1] + psum[lr0][2] + psum[lr0][3];
        float sq0  = psq[lr0][0] + psq[lr0][1] + psq[lr0][2] + psq[lr0][3];
        float sum1 = psum[lr1][0] + psum[lr1][1] + psum[lr1][2] + psum[lr1][3];
        float sq1  = psq[lr1][0] + psq[lr1][1] + psq[lr1][2] + psq[lr1][3];
        float mean0 = sum0 * (1.f / 128.f);
        float rstd0 = rsqrtf(sq0 * (1.f / 128.f) - mean0 * mean0 + 1e-5f);
        float mean1 = sum1 * (1.f / 128.f);
        float rstd1 = rsqrtf(sq1 * (1.f / 128.f) - mean1 * mean1 + 1e-5f);
        #pragma unroll
        for (int nt = 0; nt < 4; nt++) {
            int n = warp_n * 32 + nt * 8 + tig * 2;
            float g0 = ln1s[n], g1 = ln1s[n + 1];
            float bb0 = ln1b[n], bb1 = ln1b[n + 1];
            __half2 hv0 = __floats2half2_rn(
                (c3[nt][0] - mean0) * rstd0 * g0 + bb0,
                (c3[nt][1] - mean0) * rstd0 * g1 + bb1);
            __half2 hv1 = __floats2half2_rn(
                (c3[nt][2] - mean1) * rstd1 * g0 + bb0,
                (c3[nt][3] - mean1) * rstd1 * g1 + bb1);
            *reinterpret_cast<unsigned*>(&HN2[lr0][n]) = *reinterpret_cast<unsigned*>(&hv0);
            *reinterpret_cast<unsigned*>(&HN2[lr1][n]) = *reinterpret_cast<unsigned*>(&hv1);
        }

        __half (*WsA)[136] = reinterpret_cast<__half(*)[136]>(Wsraw);
        for (int chunk = 0; chunk < 3; chunk++) {
            __syncthreads();
            #pragma unroll
            for (int it = 0; it < 8; it++) {
                int idx = tid + it * 256;
                int r = idx >> 4, q = idx & 15;
                *reinterpret_cast<uint4*>(&WsA[r][q * 8]) = w4Reg[it];
            }
            __syncthreads();
            if (chunk + 1 < 3) {
                #pragma unroll
                for (int it = 0; it < 8; it++) {
                    int idx = tid + it * 256;
                    int r = idx >> 4, q = idx & 15;
                    w4Reg[it] = *reinterpret_cast<const uint4*>(
                        Win + (size_t)((chunk + 1) * 128 + r) * 128 + q * 8);
                }
            }
            float c4[4][4] = {};
            #pragma unroll
            for (int ks8 = 0; ks8 < 8; ks8++) {
                int kc = ks8 * 16;
                unsigned a[4];
                int rbase = warp_m * 16;
                a[0] = *reinterpret_cast<const unsigned*>(&HN2[rbase + g    ][kc + tig * 2]);
                a[1] = *reinterpret_cast<const unsigned*>(&HN2[rbase + g + 8][kc + tig * 2]);
                a[2] = *reinterpret_cast<const unsigned*>(&HN2[rbase + g    ][kc + tig * 2 + 8]);
                a[3] = *reinterpret_cast<const unsigned*>(&HN2[rbase + g + 8][kc + tig * 2 + 8]);
                #pragma unroll
                for (int nt = 0; nt < 4; nt++) {
                    unsigned bfr[2];
                    int nrow = warp_n * 32 + nt * 8 + g;
                    bfr[0] = *reinterpret_cast<const unsigned*>(&WsA[nrow][kc + tig * 2]);
                    bfr[1] = *reinterpret_cast<const unsigned*>(&WsA[nrow][kc + tig * 2 + 8]);
                    mma16816(c4[nt], a, bfr);
                }
            }
            #pragma unroll
            for (int nt = 0; nt < 4; nt++) {
                int nl = warp_n * 32 + nt * 8 + tig * 2;
                int n = chunk * 128 + nl;
                float b0 = bin[n], b1v = bin[n + 1];
                float v00 = c4[nt][0] + b0, v01 = c4[nt][1] + b1v;
                float v10 = c4[nt][2] + b0, v11 = c4[nt][3] + b1v;
                if (chunk < 2) {
                    if (chunk == 0) { v00 *= QK_SCALE_L2E; v01 *= QK_SCALE_L2E;
                                      v10 *= QK_SCALE_L2E; v11 *= QK_SCALE_L2E; }
                    if (mrow0 < M) {
                        __half2 hv = __floats2half2_rn(v00, v01);
                        *reinterpret_cast<unsigned*>(qkvh + (size_t)mrow0 * 384 + n)
                            = *reinterpret_cast<unsigned*>(&hv);
                    }
                    if (mrow1 < M) {
                        __half2 hv = __floats2half2_rn(v10, v11);
                        *reinterpret_cast<unsigned*>(qkvh + (size_t)mrow1 * 384 + n)
                            = *reinterpret_cast<unsigned*>(&hv);
                    }
                } else {
                    int hh = nl >> 5, dd = nl & 31;
                    if (mrow0 < M) {
                        int bb = mrow0 / S_LEN, ss = mrow0 % S_LEN;
                        __half* vb = vT + ((size_t)(bb * N_HEADS + hh) * DHEAD + dd) * VT_PITCH + ss;
                        vb[0] = __float2half_rn(v00);
                        vb[VT_PITCH] = __float2half_rn(v01);
                    }
                    if (mrow1 < M) {
                        int bb = mrow1 / S_LEN, ss = mrow1 % S_LEN;
                        __half* vb = vT + ((size_t)(bb * N_HEADS + hh) * DHEAD + dd) * VT_PITCH + ss;
                        vb[0] = __float2half_rn(v10);
                        vb[VT_PITCH] = __float2half_rn(v11);
                    }
                }
            }
        }
    }
}

// ---------------- head ----------------
__global__ __launch_bounds__(64) void head_kernel(
    const float* __restrict__ h, const float* __restrict__ ls,
    const float* __restrict__ lb, const float* __restrict__ hw,
    const float* __restrict__ hb, float* __restrict__ out)
{
    int bidx = threadIdx.x >> 5;
    if (bidx >= BATCH) return;
    int lane = threadIdx.x & 31;
    const float* xr = h + (size_t)bidx * S_LEN * D_MODEL;
    float4 v = *reinterpret_cast<const float4*>(xr + lane * 4);
    float sum = v.x + v.y + v.z + v.w;
    #pragma unroll
    for (int o = 16; o; o >>= 1) sum += __shfl_xor_sync(0xffffffffu, sum, o);
    float mean = sum * (1.f / 128.f);
    float dx = v.x - mean, dy = v.y - mean, dz = v.z - mean, dw = v.w - mean;
    float vs = dx * dx + dy * dy + dz * dz + dw * dw;
    #pragma unroll
    for (int o = 16; o; o >>= 1) vs += __shfl_xor_sync(0xffffffffu, vs, o);
    float rstd = rsqrtf(vs * (1.f / 128.f) + 1e-5f);
    float4 s4 = *reinterpret_cast<const float4*>(ls + lane * 4);
    float4 b4 = *reinterpret_cast<const float4*>(lb + lane * 4);
    float4 w4 = *reinterpret_cast<const float4*>(hw + lane * 4);
    float dot = (dx * rstd * s4.x + b4.x) * w4.x
              + (dy * rstd * s4.y + b4.y) * w4.y
              + (dz * rstd * s4.z + b4.z) * w4.z
              + (dw * rstd * s4.w + b4.w) * w4.w;
    #pragma unroll
    for (int o = 16; o; o >>= 1) dot += __shfl_xor_sync(0xffffffffu, dot, o);
    if (lane == 0) out[bidx] = dot + hb[0];
}

// ---------------- launch ----------------
extern "C" void kernel_launch(void* const* d_in, const int* in_sizes, int n_in,
                              void* d_out, int out_size)
{
    const float* x        = (const float*)d_in[0];
    const float* embed_w  = (const float*)d_in[1];
    const float* embed_b  = (const float*)d_in[2];
    const float* pos_emb  = (const float*)d_in[3];
    const float* cls      = (const float*)d_in[4];
    const float* in_w     = (const float*)d_in[5];
    const float* in_b     = (const float*)d_in[6];
    const float* out_w    = (const float*)d_in[7];
    const float* out_b    = (const float*)d_in[8];
    const float* ln1_s    = (const float*)d_in[9];
    const float* ln1_b    = (const float*)d_in[10];
    const float* ln2_s    = (const float*)d_in[11];
    const float* ln2_b    = (const float*)d_in[12];
    const float* ff1_w    = (const float*)d_in[13];
    const float* ff1_b    = (const float*)d_in[14];
    const float* ff2_w    = (const float*)d_in[15];
    const float* ff2_b    = (const float*)d_in[16];
    const float* hln_s    = (const float*)d_in[17];
    const float* hln_b    = (const float*)d_in[18];
    const float* head_w   = (const float*)d_in[19];
    const float* head_b   = (const float*)d_in[20];
    float* outp = (float*)d_out;

    float *h, *po, *pl;
    __half *hnh, *qkvh, *vt, *wh;
    cudaGetSymbolAddress((void**)&h,     g_h);
    cudaGetSymbolAddress((void**)&hnh,   g_hnh);
    cudaGetSymbolAddress((void**)&qkvh,  g_qkvh);
    cudaGetSymbolAddress((void**)&vt,    g_vt);
    cudaGetSymbolAddress((void**)&po,    g_po);
    cudaGetSymbolAddress((void**)&pl,    g_pl);
    cudaGetSymbolAddress((void**)&wh,    g_wh);

    cudaFuncSetAttribute(mega_tail_kernel<true>,
                         cudaFuncAttributeMaxDynamicSharedMemorySize, SMEM_MEGA);
    cudaFuncSetAttribute(mega_tail_kernel<false>,
                         cudaFuncAttributeMaxDynamicSharedMemorySize, SMEM_MEGA);

    const int M = MROWS;
    const int MB128 = (M + 127) / 128;
    const int MB32  = (M + 31) / 32;
    const int QTILES = (S_LEN + BQ - 1) / BQ;

    convw_all_kernel<<<(CW_TOTAL + 255) / 256, 256>>>(in_w, out_w, ff1_w, ff2_w, wh);

    embed_ln_kernel<<<dim3(S_LEN, BATCH), 128>>>(
        x, embed_w, embed_b, pos_emb, cls, ln1_s, ln1_b, h, hnh);

    qkv_gemm_kernel<<<dim3(384 / 64, MB128), 256>>>(
        hnh, wh + WOFF_IN, in_b, qkvh, vt, M);

    for (int i = 0; i < NL; i++) {
        attn_kernel<<<dim3(QTILES * SPLITS, N_HEADS, BATCH), 256>>>(qkvh, vt, po, pl);
        if (i + 1 < NL) {
            mega_tail_kernel<true><<<MB32, 256, SMEM_MEGA>>>(
                po, pl,
                wh + WOFF_OUT + (size_t)i * 128 * 128, out_b + (size_t)i * 128,
                ln2_s + i * D_MODEL, ln2_b + i * D_MODEL,
                wh + WOFF_FF1 + (size_t)i * 512 * 128, ff1_b + (size_t)i * 512,
                wh + WOFF_FF2 + (size_t)i * 128 * 512, ff2_b + (size_t)i * 128,
                ln1_s + (i + 1) * D_MODEL, ln1_b + (i + 1) * D_MODEL,
                wh + WOFF_IN + (size_t)(i + 1) * 384 * 128, in_b + (size_t)(i + 1) * 384,
                h, qkvh, vt, M);
        } else {
            mega_tail_kernel<false><<<MB32, 256, SMEM_MEGA>>>(
                po, pl,
                wh + WOFF_OUT + (size_t)i * 128 * 128, out_b + (size_t)i * 128,
                ln2_s + i * D_MODEL, ln2_b + i * D_MODEL,
                wh + WOFF_FF1 + (size_t)i * 512 * 128, ff1_b + (size_t)i * 512,
                wh + WOFF_FF2 + (size_t)i * 128 * 512, ff2_b + (size_t)i * 128,
                nullptr, nullptr, nullptr, nullptr,
                h, nullptr, nullptr, M);
        }
    }

    head_kernel<<<1, 64>>>(h, hln_s, hln_b, head_w, head_b, outp);
}